// round 14
// baseline (speedup 1.0000x reference)
#include <cuda_runtime.h>
#include <math.h>

#define SP   1728
#define TOK  1728
#define BATCH 4
#define NH   4
#define LAMBDA_INIT 0.55605820416f
#define ONE_MINUS_LAMBDA 0.44394179584f
#define EPS 1e-5f

typedef unsigned long long ull;

// ---------------- packed f32x2 helpers ----------------
__device__ __forceinline__ ull pk2(float lo, float hi) {
    ull r; asm("mov.b64 %0,{%1,%2};" : "=l"(r) : "f"(lo), "f"(hi)); return r;
}
__device__ __forceinline__ void upk2(ull v, float& lo, float& hi) {
    asm("mov.b64 {%0,%1},%2;" : "=f"(lo), "=f"(hi) : "l"(v));
}
__device__ __forceinline__ ull fma2(ull a, ull b, ull c) {
    ull d; asm("fma.rn.f32x2 %0,%1,%2,%3;" : "=l"(d) : "l"(a), "l"(b), "l"(c)); return d;
}
__device__ __forceinline__ ull mul2(ull a, ull b) {
    ull d; asm("mul.rn.f32x2 %0,%1,%2;" : "=l"(d) : "l"(a), "l"(b)); return d;
}
__device__ __forceinline__ ull add2(ull a, ull b) {
    ull d; asm("add.rn.f32x2 %0,%1,%2;" : "=l"(d) : "l"(a), "l"(b)); return d;
}

// ---------------- device scratch ----------------
__device__ float g_up  [BATCH*64*SP];
__device__ float g_low [BATCH*64*SP];
__device__ float g_q1  [BATCH*NH*TOK*16];
__device__ float g_q2  [BATCH*NH*TOK*16];
__device__ float g_k1  [BATCH*NH*TOK*16];
__device__ float g_k2  [BATCH*NH*TOK*16];
__device__ float g_v   [BATCH*NH*TOK*32];
__device__ ull   g_part[16*27*7*33*64];   // [bh][qb][chunk][elem33][q64]
__device__ float g_a1  [BATCH*TOK*64];    // == (B,64,12,12,12) raw reshape
__device__ float g_y1  [BATCH*256*SP];
__device__ float g_y2  [BATCH*192*SP];
__device__ ulonglong2 g_wtA[64*9*128];    // taps 0,1 packed (oc=t, oc=t+128), dense
__device__ ull        g_wtB[64*9*128];    // tap 2 packed, dense
__device__ float g_cp  [BATCH*72*256];    // conv per-block channel partial sums
__device__ float g_pool[BATCH*512];
__device__ float g_smx [BATCH*512];

// ---------------- prep: wtrans + pw_sq1 + pw_sq2 packed in one launch --------
__global__ __launch_bounds__(192) void prep_kernel(
        const float* __restrict__ x, const float* __restrict__ w_sq1,
        const float* __restrict__ w_sq2, const float* __restrict__ w_conv) {
    __shared__ ull wsh2[4*128];
    int bx = blockIdx.x;
    int tid = threadIdx.x;
    if (bx < 576) {
        int mode = (bx >= 288) ? 1 : 0;
        int i = bx - mode*288;
        int b = i & 3; i >>= 2;
        int og = i & 7; i >>= 3;
        int zc = i;                          // 0..8
        const float* w = mode ? w_sq2 : w_sq1;
        for (int ii = tid; ii < 4*128; ii += 192) {
            int p = ii >> 7, c = ii & 127;
            wsh2[ii] = pk2(w[(size_t)(og*8 + 2*p)*128 + c],
                           w[(size_t)(og*8 + 2*p + 1)*128 + c]);
        }
        __syncthreads();
        const float* inb = x + (size_t)b*256*SP + (size_t)(mode ? 128 : 0)*SP;
        float* outb = (mode ? g_low : g_up) + (size_t)b*64*SP + (size_t)og*8*SP;
        int s = zc*192 + tid;
        ull acc[4];
#pragma unroll
        for (int p = 0; p < 4; p++) acc[p] = 0ull;
        for (int i2 = 0; i2 < 128; i2 += 4) {
            ull xp0 = pk2(inb[(i2+0)*SP + s], inb[(i2+0)*SP + s]);
            ull xp1 = pk2(inb[(i2+1)*SP + s], inb[(i2+1)*SP + s]);
            ull xp2 = pk2(inb[(i2+2)*SP + s], inb[(i2+2)*SP + s]);
            ull xp3 = pk2(inb[(i2+3)*SP + s], inb[(i2+3)*SP + s]);
#pragma unroll
            for (int p = 0; p < 4; p++) {
                ulonglong2 wa = *(const ulonglong2*)&wsh2[p*128 + i2];
                ulonglong2 wb = *(const ulonglong2*)&wsh2[p*128 + i2 + 2];
                acc[p] = fma2(wa.x, xp0, acc[p]);
                acc[p] = fma2(wa.y, xp1, acc[p]);
                acc[p] = fma2(wb.x, xp2, acc[p]);
                acc[p] = fma2(wb.y, xp3, acc[p]);
            }
        }
#pragma unroll
        for (int p = 0; p < 4; p++) {
            float lo, hi; upk2(acc[p], lo, hi);
            outb[(2*p)*SP + s]   = lo;
            outb[(2*p+1)*SP + s] = hi;
        }
    } else {
        int idx = (bx - 576)*192 + tid;      // < 64*9*128
        int t = idx & 127;
        int icr = idx >> 7;                  // ic*9 + r
        int ic = icr / 9, r = icr % 9;
        const float* s0 = w_conv + (size_t)t*1728 + ic*27 + r*3;
        const float* s1 = w_conv + (size_t)(t+128)*1728 + ic*27 + r*3;
        ulonglong2 w01;
        w01.x = pk2(s0[0], s1[0]);
        w01.y = pk2(s0[1], s1[1]);
        g_wtA[idx] = w01;
        g_wtB[idx] = pk2(s0[2], s1[2]);
    }
}

// ---------------- pointwise conv (mode 2 only: g_low -> g_y2, NI=64) --------
__global__ __launch_bounds__(192) void pw_kernel(const float* __restrict__ w) {
    __shared__ ull wsh2[4*64];
    int b = blockIdx.x, og = blockIdx.y, tid = threadIdx.x;
    for (int i = tid; i < 4*64; i += 192) {
        int p = i >> 6, c = i & 63;
        wsh2[i] = pk2(w[(size_t)(og*8 + 2*p)*64 + c],
                      w[(size_t)(og*8 + 2*p + 1)*64 + c]);
    }
    __syncthreads();
    const float* inb = g_low + (size_t)b*64*SP;
    float* outb = g_y2 + (size_t)b*192*SP + (size_t)og*8*SP;
    int s = blockIdx.z*192 + tid;
    ull acc[4];
#pragma unroll
    for (int p = 0; p < 4; p++) acc[p] = 0ull;
    for (int i = 0; i < 64; i += 4) {
        ull xp0 = pk2(inb[(i+0)*SP + s], inb[(i+0)*SP + s]);
        ull xp1 = pk2(inb[(i+1)*SP + s], inb[(i+1)*SP + s]);
        ull xp2 = pk2(inb[(i+2)*SP + s], inb[(i+2)*SP + s]);
        ull xp3 = pk2(inb[(i+3)*SP + s], inb[(i+3)*SP + s]);
#pragma unroll
        for (int p = 0; p < 4; p++) {
            ulonglong2 wa = *(const ulonglong2*)&wsh2[p*64 + i];
            ulonglong2 wb = *(const ulonglong2*)&wsh2[p*64 + i + 2];
            acc[p] = fma2(wa.x, xp0, acc[p]);
            acc[p] = fma2(wa.y, xp1, acc[p]);
            acc[p] = fma2(wb.x, xp2, acc[p]);
            acc[p] = fma2(wb.y, xp3, acc[p]);
        }
    }
#pragma unroll
    for (int p = 0; p < 4; p++) {
        float lo, hi; upk2(acc[p], lo, hi);
        outb[(2*p)*SP + s]   = lo;
        outb[(2*p+1)*SP + s] = hi;
    }
}

// ---------------- QKV projection (g_up raw-reshaped to (B*T,64)) -------------
__global__ __launch_bounds__(384) void qkv_kernel(
        const float* __restrict__ wq1, const float* __restrict__ wq2,
        const float* __restrict__ wk1, const float* __restrict__ wk2,
        const float* __restrict__ wv) {
    __shared__ float xsh[16*64];
    int tid = threadIdx.x;
    int bt0 = blockIdx.x * 16;
    if (tid < 256) ((float4*)xsh)[tid] = ((const float4*)g_up)[bt0*16 + tid];
    __syncthreads();

    int r = tid;
    int b = bt0 / TOK, t0 = bt0 % TOK;
    const float* wrow; float sc = 1.f; float* obase; int ostride;
    if (r < 64) {
        wrow = wq1 + r*64; sc = 0.25f; ostride = 16;
        obase = g_q1 + ((size_t)(b*NH + (r>>4))*TOK + t0)*16 + (r&15);
    } else if (r < 128) {
        int rr = r-64; wrow = wq2 + rr*64; sc = 0.25f; ostride = 16;
        obase = g_q2 + ((size_t)(b*NH + (rr>>4))*TOK + t0)*16 + (rr&15);
    } else if (r < 192) {
        int rr = r-128; wrow = wk1 + rr*64; ostride = 16;
        obase = g_k1 + ((size_t)(b*NH + (rr>>4))*TOK + t0)*16 + (rr&15);
    } else if (r < 256) {
        int rr = r-192; wrow = wk2 + rr*64; ostride = 16;
        obase = g_k2 + ((size_t)(b*NH + (rr>>4))*TOK + t0)*16 + (rr&15);
    } else {
        int rr = r-256; wrow = wv + rr*64; ostride = 32;
        obase = g_v + ((size_t)(b*NH + (rr>>5))*TOK + t0)*32 + (rr&31);
    }
    float wr[64];
#pragma unroll
    for (int i4 = 0; i4 < 16; i4++) {
        float4 w4 = ((const float4*)wrow)[i4];
        wr[i4*4+0]=w4.x*sc; wr[i4*4+1]=w4.y*sc; wr[i4*4+2]=w4.z*sc; wr[i4*4+3]=w4.w*sc;
    }
    float acc[16];
#pragma unroll
    for (int t = 0; t < 16; t++) acc[t] = 0.f;
    for (int i = 0; i < 64; i += 4) {
#pragma unroll
        for (int t = 0; t < 16; t++) {
            float4 xv = *(const float4*)&xsh[t*64 + i];
            acc[t] += wr[i]*xv.x + wr[i+1]*xv.y + wr[i+2]*xv.z + wr[i+3]*xv.w;
        }
    }
#pragma unroll
    for (int t = 0; t < 16; t++) obase[(size_t)t*ostride] = acc[t];
}

// ---------------- attention partial: one 256-key chunk per block -------------
// R9 structure; k dot-products via LDS.128 (single reused temp), v via LDS.64.
__global__ __launch_bounds__(256) void attn_part_kernel() {
    extern __shared__ float smem[];
    int tid = threadIdx.x;
    int qi = tid >> 6, ql = tid & 63;
    int bxr = 104 - blockIdx.x;         // heavy (qb,chunk) first
    int qb = 0, nchw;
    for (;; qb++) { nchw = (qb >> 2) + 1; if (bxr < nchw) break; bxr -= nchw; }
    int chunk = bxr;
    int bh = blockIdx.y;
    int q = qb*64 + ql;
    int nt = qb + 1;                    // total key tiles for this qb
    int tiles = nt - chunk*4; if (tiles > 4) tiles = 4;

    const float* k1base = g_k1 + (size_t)bh*TOK*16;
    const float* k2base = g_k2 + (size_t)bh*TOK*16;
    const float* vbase  = g_v  + (size_t)bh*TOK*32;

    for (int i = tid; i < tiles*1024; i += 256) {
        int tI = i >> 10, j = i & 1023;
        int kt = chunk*4 + tI;
        float4 val;
        if (j < 256)      val = ((const float4*)(k1base + (size_t)kt*64*16))[j];
        else if (j < 512) val = ((const float4*)(k2base + (size_t)kt*64*16))[j-256];
        else              val = ((const float4*)(vbase  + (size_t)kt*64*32))[j-512];
        ((float4*)&smem[tI*4096])[j] = val;
    }

    const ulonglong2* qp1 = (const ulonglong2*)(g_q1 + ((size_t)bh*TOK + q)*16);
    const ulonglong2* qp2 = (const ulonglong2*)(g_q2 + ((size_t)bh*TOK + q)*16);
    ull q1p[8], q2p[8];
#pragma unroll
    for (int i = 0; i < 4; i++) {
        ulonglong2 a = qp1[i]; q1p[i*2] = a.x; q1p[i*2+1] = a.y;
        ulonglong2 c = qp2[i]; q2p[i*2] = c.x; q2p[i*2+1] = c.y;
    }
    ull acc1p[16], acc2p[16];
#pragma unroll
    for (int i = 0; i < 16; i++) { acc1p[i] = 0ull; acc2p[i] = 0ull; }
    float l1 = 0.f, l2 = 0.f;
    __syncthreads();

    int kt = chunk*4 + qi;
    if (kt < nt) {
        int k0 = kt*64;
        int jn = q - k0 + 1;
        if (jn > 64) jn = 64;
        const float* tb = &smem[qi*4096];
        const ulonglong2* k1w = (const ulonglong2*)tb;
        const ulonglong2* k2w = (const ulonglong2*)(tb + 1024);
        const ull* vs  = (const ull*)(tb + 2048);
        for (int j = 0; j < jn; j++) {
            ulonglong2 t;
            t = k1w[j*4 + 0];
            ull sp1 = mul2(q1p[0], t.x);
            sp1 = fma2(q1p[1], t.y, sp1);
            t = k1w[j*4 + 1];
            sp1 = fma2(q1p[2], t.x, sp1);
            sp1 = fma2(q1p[3], t.y, sp1);
            t = k1w[j*4 + 2];
            sp1 = fma2(q1p[4], t.x, sp1);
            sp1 = fma2(q1p[5], t.y, sp1);
            t = k1w[j*4 + 3];
            sp1 = fma2(q1p[6], t.x, sp1);
            sp1 = fma2(q1p[7], t.y, sp1);
            t = k2w[j*4 + 0];
            ull sp2 = mul2(q2p[0], t.x);
            sp2 = fma2(q2p[1], t.y, sp2);
            t = k2w[j*4 + 1];
            sp2 = fma2(q2p[2], t.x, sp2);
            sp2 = fma2(q2p[3], t.y, sp2);
            t = k2w[j*4 + 2];
            sp2 = fma2(q2p[4], t.x, sp2);
            sp2 = fma2(q2p[5], t.y, sp2);
            t = k2w[j*4 + 3];
            sp2 = fma2(q2p[6], t.x, sp2);
            sp2 = fma2(q2p[7], t.y, sp2);
            float alo, ahi, blo, bhi;
            upk2(sp1, alo, ahi);
            upk2(sp2, blo, bhi);
            float p1 = __expf(alo + ahi);
            float p2 = __expf(blo + bhi);
            l1 += p1; l2 += p2;
            ull pp1 = pk2(p1, p1), pp2 = pk2(p2, p2);
            const ull* vv = &vs[j*16];
#pragma unroll
            for (int i = 0; i < 16; i++) {
                acc1p[i] = fma2(pp1, vv[i], acc1p[i]);
                acc2p[i] = fma2(pp2, vv[i], acc2p[i]);
            }
        }
    }

    __syncthreads();
    ull* cmb = (ull*)smem;              // overlay: [3][33][64]
    if (qi) {
#pragma unroll
        for (int i = 0; i < 16; i++) {
            cmb[(size_t)(qi-1)*2112 + i*64 + ql]      = acc1p[i];
            cmb[(size_t)(qi-1)*2112 + (16+i)*64 + ql] = acc2p[i];
        }
        cmb[(size_t)(qi-1)*2112 + 32*64 + ql] = pk2(l1, l2);
    }
    __syncthreads();
    if (qi) return;

#pragma unroll
    for (int i = 0; i < 16; i++) {
#pragma unroll
        for (int c = 0; c < 3; c++) {
            acc1p[i] = add2(acc1p[i], cmb[(size_t)c*2112 + i*64 + ql]);
            acc2p[i] = add2(acc2p[i], cmb[(size_t)c*2112 + (16+i)*64 + ql]);
        }
    }
    ull lp = pk2(l1, l2);
#pragma unroll
    for (int c = 0; c < 3; c++) lp = add2(lp, cmb[(size_t)c*2112 + 32*64 + ql]);

    ull* pb = &g_part[(size_t)((bh*27 + qb)*7 + chunk)*2112 + ql];
#pragma unroll
    for (int i = 0; i < 16; i++) {
        pb[i*64]      = acc1p[i];
        pb[(16+i)*64] = acc2p[i];
    }
    pb[32*64] = lp;
}

// ---------------- fused combine + lambda + LN + output projection ------------
__global__ __launch_bounds__(256) void comb_proj_kernel(
        const float* __restrict__ lq1, const float* __restrict__ lk1,
        const float* __restrict__ lq2, const float* __restrict__ lk2,
        const float* __restrict__ w_c) {
    __shared__ float ys[64*132];       // padded rows: 132 floats
    int tid = threadIdx.x;
    int qb = blockIdx.x, b = blockIdx.y;
    int h = tid >> 6, ql = tid & 63;
    int bh = b*NH + h;
    int nch = (qb >> 2) + 1;

    ull acc1p[16], acc2p[16];
#pragma unroll
    for (int i = 0; i < 16; i++) { acc1p[i] = 0ull; acc2p[i] = 0ull; }
    ull lp = 0ull;
    const ull* base = &g_part[(size_t)((bh*27 + qb)*7)*2112 + ql];
    for (int c = 0; c < nch; c++) {
        const ull* pc = base + (size_t)c*2112;
#pragma unroll
        for (int i = 0; i < 16; i++) {
            acc1p[i] = add2(acc1p[i], pc[i*64]);
            acc2p[i] = add2(acc2p[i], pc[(16+i)*64]);
        }
        lp = add2(lp, pc[32*64]);
    }
    float l1, l2; upk2(lp, l1, l2);

    float acc1[32], acc2[32];
#pragma unroll
    for (int i = 0; i < 16; i++) {
        upk2(acc1p[i], acc1[i*2], acc1[i*2+1]);
        upk2(acc2p[i], acc2[i*2], acc2[i*2+1]);
    }

    float s1 = 0.f, s2 = 0.f;
#pragma unroll
    for (int i = 0; i < 16; i++) {
        s1 += lq1[h*16+i]*lk1[h*16+i];
        s2 += lq2[h*16+i]*lk2[h*16+i];
    }
    float lam = expf(s1) - expf(s2) + LAMBDA_INIT;
    float inv1 = 1.0f/l1, inv2 = 1.0f/l2;

    float y[32], mu = 0.f;
#pragma unroll
    for (int d = 0; d < 32; d++) {
        y[d] = acc1[d]*inv1 - lam*(acc2[d]*inv2);
        mu += y[d];
    }
    mu *= (1.0f/32.0f);
    float var = 0.f;
#pragma unroll
    for (int d = 0; d < 32; d++) { float t = y[d]-mu; var += t*t; }
    var *= (1.0f/32.0f);
    float scl = rsqrtf(var + EPS) * ONE_MINUS_LAMBDA;

    float* yp = &ys[ql*132 + h*32];
#pragma unroll
    for (int d4 = 0; d4 < 8; d4++) {
        float4 o;
        o.x = (y[d4*4+0]-mu)*scl; o.y = (y[d4*4+1]-mu)*scl;
        o.z = (y[d4*4+2]-mu)*scl; o.w = (y[d4*4+3]-mu)*scl;
        ((float4*)yp)[d4] = o;
    }
    __syncthreads();

    // phase 2: projection. thread = (tg 0..3, oc 0..63), 16 tokens each.
    int oc = tid & 63;
    int tg = tid >> 6;
    float acc[16];
#pragma unroll
    for (int t = 0; t < 16; t++) acc[t] = 0.f;
    for (int i = 0; i < 128; i += 4) {
        float4 w4 = *(const float4*)&w_c[oc*128 + i];
#pragma unroll
        for (int t = 0; t < 16; t++) {
            float4 xv = *(const float4*)&ys[(tg*16 + t)*132 + i];
            acc[t] += w4.x*xv.x + w4.y*xv.y + w4.z*xv.z + w4.w*xv.w;
        }
    }
    float* ob = g_a1 + ((size_t)(b*TOK + qb*64 + tg*16))*64 + oc;
#pragma unroll
    for (int t = 0; t < 16; t++) ob[(size_t)t*64] = acc[t];
}

// ---------------- 3D conv 64->256: single-load weights, (dz,dy)->ly order ----
__global__ __launch_bounds__(128) void conv_kernel(const float* __restrict__ b_conv) {
    __shared__ float sin[64*3*4*16];   // [ic][dz][ry][16]
    int tid = threadIdx.x;
    int zyg = blockIdx.x;              // 12*6
    int b = blockIdx.y;
    int z = zyg / 6, y0 = (zyg % 6) * 2;

    for (int R = tid; R < 768; R += 128) {
        int ic = R / 12, rem = R % 12;
        int dz = rem >> 2, ry = rem & 3;
        int zz = z + dz - 1, yy = y0 + ry - 1;
        float* dst = &sin[R*16];
        if (zz < 0 || zz >= 12 || yy < 0 || yy >= 12) {
#pragma unroll
            for (int i = 0; i < 16; i++) dst[i] = 0.f;
        } else {
            const float* src = g_a1 + (size_t)b*110592 + ic*1728 + zz*144 + yy*12;
            dst[0] = 0.f;
#pragma unroll
            for (int i = 0; i < 12; i++) dst[1+i] = src[i];
            dst[13] = 0.f; dst[14] = 0.f; dst[15] = 0.f;
        }
    }
    __syncthreads();

    int t = tid;                       // oc pair (t, t+128)
    ull accp[2][12];
#pragma unroll
    for (int ly = 0; ly < 2; ly++)
#pragma unroll
        for (int x = 0; x < 12; x++) accp[ly][x] = 0ull;

    for (int ic = 0; ic < 64; ic++) {
#pragma unroll
        for (int dz = 0; dz < 3; dz++) {
            const float* rbase = &sin[((ic*3 + dz)*4)*16];
#pragma unroll
            for (int dy = 0; dy < 3; dy++) {
                int tap = ic*9 + dz*3 + dy;
                ulonglong2 w01 = g_wtA[(size_t)tap*128 + t];   // coalesced 16B
                ull        w2  = g_wtB[(size_t)tap*128 + t];   // coalesced 8B
#pragma unroll
                for (int ly = 0; ly < 2; ly++) {
                    int r = dy + ly;   // input row index 0..3, compile-time
                    const float4* v4 = (const float4*)&rbase[r*16];
                    float4 a = v4[0], bb = v4[1], c = v4[2], d = v4[3];
                    float v[16] = {a.x,a.y,a.z,a.w, bb.x,bb.y,bb.z,bb.w,
                                   c.x,c.y,c.z,c.w, d.x,d.y,d.z,d.w};
                    ull vb[14];
#pragma unroll
                    for (int x = 0; x < 14; x++) vb[x] = pk2(v[x], v[x]);
#pragma unroll
                    for (int x = 0; x < 12; x++) {
                        accp[ly][x] = fma2(w01.x, vb[x],   accp[ly][x]);
                        accp[ly][x] = fma2(w01.y, vb[x+1], accp[ly][x]);
                        accp[ly][x] = fma2(w2,    vb[x+2], accp[ly][x]);
                    }
                }
            }
        }
    }

    float bias0 = b_conv[t], bias1 = b_conv[t+128];
    float ps0 = 0.f, ps1 = 0.f;        // pool partials (bias included)
#pragma unroll
    for (int ly = 0; ly < 2; ly++) {
        float r0[12], r1[12];
#pragma unroll
        for (int x = 0; x < 12; x++) {
            float lo, hi; upk2(accp[ly][x], lo, hi);
            r0[x] = lo + bias0; r1[x] = hi + bias1;
            ps0 += r0[x];      ps1 += r1[x];
        }
        float* op0 = g_y1 + ((size_t)b*256 + t)*1728 + z*144 + (y0+ly)*12;
        float* op1 = g_y1 + ((size_t)b*256 + t + 128)*1728 + z*144 + (y0+ly)*12;
#pragma unroll
        for (int x4 = 0; x4 < 3; x4++) {
            ((float4*)op0)[x4] = make_float4(r0[x4*4], r0[x4*4+1], r0[x4*4+2], r0[x4*4+3]);
            ((float4*)op1)[x4] = make_float4(r1[x4*4], r1[x4*4+1], r1[x4*4+2], r1[x4*4+3]);
        }
    }
    g_cp[((size_t)b*72 + zyg)*256 + t]       = ps0;
    g_cp[((size_t)b*72 + zyg)*256 + t + 128] = ps1;
}

// ---------------- channel pooling ----------------
__global__ __launch_bounds__(128) void pool_kernel() {
    int ch = blockIdx.x & 511;
    int b = blockIdx.x >> 9;
    int tid = threadIdx.x;
    float s = 0.f;
    if (ch < 256) {
        if (tid < 72) s = g_cp[((size_t)b*72 + tid)*256 + ch];
    } else {
        const float* src;
        if (ch < 448) src = g_y2 + ((size_t)b*192 + (ch-256))*SP;
        else          src = g_low + ((size_t)b*64 + (ch-448))*SP;
        for (int i = tid; i < SP; i += 128) s += src[i];
    }
#pragma unroll
    for (int off = 16; off > 0; off >>= 1)
        s += __shfl_down_sync(0xffffffffu, s, off);
    __shared__ float red[4];
    if ((tid & 31) == 0) red[tid >> 5] = s;
    __syncthreads();
    if (tid == 0)
        g_pool[blockIdx.x] = (red[0]+red[1]+red[2]+red[3]) * (1.0f/SP);
}

// ---------------- softmax over 512 channels ----------------
__global__ __launch_bounds__(512) void smx_kernel() {
    __shared__ float sm[512];
    int b = blockIdx.x, tid = threadIdx.x;
    float p = g_pool[b*512 + tid];
    sm[tid] = p;
    __syncthreads();
    for (int off = 256; off > 0; off >>= 1) {
        if (tid < off) sm[tid] = fmaxf(sm[tid], sm[tid+off]);
        __syncthreads();
    }
    float mx = sm[0];
    __syncthreads();
    float e = expf(p - mx);
    sm[tid] = e;
    __syncthreads();
    for (int off = 256; off > 0; off >>= 1) {
        if (tid < off) sm[tid] += sm[tid+off];
        __syncthreads();
    }
    g_smx[b*512 + tid] = e / sm[0];
}

// ---------------- final gate + fold ----------------
__global__ __launch_bounds__(256) void final_kernel(float* __restrict__ out) {
    int i = blockIdx.x * 256 + threadIdx.x;   // over 4*256*1728
    int s = i % SP;
    int c = (i / SP) & 255;
    int b = i / (SP*256);
    float v1 = g_y1[i];
    float w1 = g_smx[b*512 + c];
    float v2, w2 = g_smx[b*512 + 256 + c];
    if (c < 192) v2 = g_y2[((size_t)b*192 + c)*SP + s];
    else         v2 = g_low[((size_t)b*64 + (c-192))*SP + s];
    out[i] = w1*v1 + w2*v2;
}

// ---------------- launch ----------------
extern "C" void kernel_launch(void* const* d_in, const int* in_sizes, int n_in,
                              void* d_out, int out_size) {
    const float* x      = (const float*)d_in[0];
    const float* w_sq1  = (const float*)d_in[1];
    const float* w_sq2  = (const float*)d_in[2];
    const float* w_pwc2 = (const float*)d_in[3];
    const float* w_conv = (const float*)d_in[4];
    const float* b_conv = (const float*)d_in[5];
    const float* w_q1   = (const float*)d_in[6];
    const float* w_q2   = (const float*)d_in[7];
    const float* w_k1   = (const float*)d_in[8];
    const float* w_k2   = (const float*)d_in[9];
    const float* w_v    = (const float*)d_in[10];
    const float* w_c    = (const float*)d_in[11];
    const float* lq1    = (const float*)d_in[12];
    const float* lk1    = (const float*)d_in[13];
    const float* lq2    = (const float*)d_in[14];
    const float* lk2    = (const float*)d_in[15];
    float* out = (float*)d_out;

    cudaFuncSetAttribute(attn_part_kernel,
                         cudaFuncAttributeMaxDynamicSharedMemorySize, 65536);

    prep_kernel<<<960, 192>>>(x, w_sq1, w_sq2, w_conv);
    qkv_kernel<<<432, 384>>>(w_q1, w_q2, w_k1, w_k2, w_v);
    pw_kernel<<<dim3(4,24,9), 192>>>(w_pwc2);
    attn_part_kernel<<<dim3(105,16), 256, 65536>>>();
    comb_proj_kernel<<<dim3(27,4), 256>>>(lq1, lk1, lq2, lk2, w_c);
    conv_kernel<<<dim3(72,4), 128>>>(b_conv);
    pool_kernel<<<2048, 128>>>();
    smx_kernel<<<4, 512>>>();
    final_kernel<<<6912, 256>>>(out);
}

// round 15
// speedup vs baseline: 1.0631x; 1.0631x over previous
#include <cuda_runtime.h>
#include <math.h>

#define SP   1728
#define TOK  1728
#define BATCH 4
#define NH   4
#define LAMBDA_INIT 0.55605820416f
#define ONE_MINUS_LAMBDA 0.44394179584f
#define EPS 1e-5f

typedef unsigned long long ull;

// ---------------- packed f32x2 helpers ----------------
__device__ __forceinline__ ull pk2(float lo, float hi) {
    ull r; asm("mov.b64 %0,{%1,%2};" : "=l"(r) : "f"(lo), "f"(hi)); return r;
}
__device__ __forceinline__ void upk2(ull v, float& lo, float& hi) {
    asm("mov.b64 {%0,%1},%2;" : "=f"(lo), "=f"(hi) : "l"(v));
}
__device__ __forceinline__ ull fma2(ull a, ull b, ull c) {
    ull d; asm("fma.rn.f32x2 %0,%1,%2,%3;" : "=l"(d) : "l"(a), "l"(b), "l"(c)); return d;
}
__device__ __forceinline__ ull mul2(ull a, ull b) {
    ull d; asm("mul.rn.f32x2 %0,%1,%2;" : "=l"(d) : "l"(a), "l"(b)); return d;
}
__device__ __forceinline__ ull add2(ull a, ull b) {
    ull d; asm("add.rn.f32x2 %0,%1,%2;" : "=l"(d) : "l"(a), "l"(b)); return d;
}

// ---------------- device scratch ----------------
__device__ float g_up  [BATCH*64*SP];
__device__ float g_low [BATCH*64*SP];
__device__ float g_q1  [BATCH*NH*TOK*16];
__device__ float g_q2  [BATCH*NH*TOK*16];
__device__ float g_k1  [BATCH*NH*TOK*16];
__device__ float g_k2  [BATCH*NH*TOK*16];
__device__ float g_v   [BATCH*NH*TOK*32];
__device__ ull   g_part[16*27*7*33*64];   // [bh][qb][chunk][elem33][q64]
__device__ float g_a1  [BATCH*TOK*64];    // == (B,64,12,12,12) raw reshape
__device__ float g_y1  [BATCH*256*SP];
__device__ float g_y2  [BATCH*192*SP];
__device__ ulonglong2 g_wtA[64*9*128];    // taps 0,1 packed (oc=t, oc=t+128), dense
__device__ ull        g_wtB[64*9*128];    // tap 2 packed, dense
__device__ float g_cp  [BATCH*72*256];    // conv per-block channel partial sums
__device__ float g_pool[BATCH*512];
__device__ float g_smx [BATCH*512];

// ---------------- prep: wtrans + pw_sq1 + pw_sq2 packed in one launch --------
__global__ __launch_bounds__(192) void prep_kernel(
        const float* __restrict__ x, const float* __restrict__ w_sq1,
        const float* __restrict__ w_sq2, const float* __restrict__ w_conv) {
    __shared__ ull wsh2[4*128];
    int bx = blockIdx.x;
    int tid = threadIdx.x;
    if (bx < 576) {
        int mode = (bx >= 288) ? 1 : 0;
        int i = bx - mode*288;
        int b = i & 3; i >>= 2;
        int og = i & 7; i >>= 3;
        int zc = i;                          // 0..8
        const float* w = mode ? w_sq2 : w_sq1;
        for (int ii = tid; ii < 4*128; ii += 192) {
            int p = ii >> 7, c = ii & 127;
            wsh2[ii] = pk2(w[(size_t)(og*8 + 2*p)*128 + c],
                           w[(size_t)(og*8 + 2*p + 1)*128 + c]);
        }
        __syncthreads();
        const float* inb = x + (size_t)b*256*SP + (size_t)(mode ? 128 : 0)*SP;
        float* outb = (mode ? g_low : g_up) + (size_t)b*64*SP + (size_t)og*8*SP;
        int s = zc*192 + tid;
        ull acc[4];
#pragma unroll
        for (int p = 0; p < 4; p++) acc[p] = 0ull;
        for (int i2 = 0; i2 < 128; i2 += 4) {
            ull xp0 = pk2(inb[(i2+0)*SP + s], inb[(i2+0)*SP + s]);
            ull xp1 = pk2(inb[(i2+1)*SP + s], inb[(i2+1)*SP + s]);
            ull xp2 = pk2(inb[(i2+2)*SP + s], inb[(i2+2)*SP + s]);
            ull xp3 = pk2(inb[(i2+3)*SP + s], inb[(i2+3)*SP + s]);
#pragma unroll
            for (int p = 0; p < 4; p++) {
                ulonglong2 wa = *(const ulonglong2*)&wsh2[p*128 + i2];
                ulonglong2 wb = *(const ulonglong2*)&wsh2[p*128 + i2 + 2];
                acc[p] = fma2(wa.x, xp0, acc[p]);
                acc[p] = fma2(wa.y, xp1, acc[p]);
                acc[p] = fma2(wb.x, xp2, acc[p]);
                acc[p] = fma2(wb.y, xp3, acc[p]);
            }
        }
#pragma unroll
        for (int p = 0; p < 4; p++) {
            float lo, hi; upk2(acc[p], lo, hi);
            outb[(2*p)*SP + s]   = lo;
            outb[(2*p+1)*SP + s] = hi;
        }
    } else {
        int idx = (bx - 576)*192 + tid;      // < 64*9*128
        int t = idx & 127;
        int icr = idx >> 7;                  // ic*9 + r
        int ic = icr / 9, r = icr % 9;
        const float* s0 = w_conv + (size_t)t*1728 + ic*27 + r*3;
        const float* s1 = w_conv + (size_t)(t+128)*1728 + ic*27 + r*3;
        ulonglong2 w01;
        w01.x = pk2(s0[0], s1[0]);
        w01.y = pk2(s0[1], s1[1]);
        g_wtA[idx] = w01;
        g_wtB[idx] = pk2(s0[2], s1[2]);
    }
}

// ---------------- pointwise conv (mode 2 only: g_low -> g_y2, NI=64) --------
__global__ __launch_bounds__(192) void pw_kernel(const float* __restrict__ w) {
    __shared__ ull wsh2[4*64];
    int b = blockIdx.x, og = blockIdx.y, tid = threadIdx.x;
    for (int i = tid; i < 4*64; i += 192) {
        int p = i >> 6, c = i & 63;
        wsh2[i] = pk2(w[(size_t)(og*8 + 2*p)*64 + c],
                      w[(size_t)(og*8 + 2*p + 1)*64 + c]);
    }
    __syncthreads();
    const float* inb = g_low + (size_t)b*64*SP;
    float* outb = g_y2 + (size_t)b*192*SP + (size_t)og*8*SP;
    int s = blockIdx.z*192 + tid;
    ull acc[4];
#pragma unroll
    for (int p = 0; p < 4; p++) acc[p] = 0ull;
    for (int i = 0; i < 64; i += 4) {
        ull xp0 = pk2(inb[(i+0)*SP + s], inb[(i+0)*SP + s]);
        ull xp1 = pk2(inb[(i+1)*SP + s], inb[(i+1)*SP + s]);
        ull xp2 = pk2(inb[(i+2)*SP + s], inb[(i+2)*SP + s]);
        ull xp3 = pk2(inb[(i+3)*SP + s], inb[(i+3)*SP + s]);
#pragma unroll
        for (int p = 0; p < 4; p++) {
            ulonglong2 wa = *(const ulonglong2*)&wsh2[p*64 + i];
            ulonglong2 wb = *(const ulonglong2*)&wsh2[p*64 + i + 2];
            acc[p] = fma2(wa.x, xp0, acc[p]);
            acc[p] = fma2(wa.y, xp1, acc[p]);
            acc[p] = fma2(wb.x, xp2, acc[p]);
            acc[p] = fma2(wb.y, xp3, acc[p]);
        }
    }
#pragma unroll
    for (int p = 0; p < 4; p++) {
        float lo, hi; upk2(acc[p], lo, hi);
        outb[(2*p)*SP + s]   = lo;
        outb[(2*p+1)*SP + s] = hi;
    }
}

// ---------------- QKV projection (g_up raw-reshaped to (B*T,64)) -------------
__global__ __launch_bounds__(384) void qkv_kernel(
        const float* __restrict__ wq1, const float* __restrict__ wq2,
        const float* __restrict__ wk1, const float* __restrict__ wk2,
        const float* __restrict__ wv) {
    __shared__ float xsh[16*64];
    int tid = threadIdx.x;
    int bt0 = blockIdx.x * 16;
    if (tid < 256) ((float4*)xsh)[tid] = ((const float4*)g_up)[bt0*16 + tid];
    __syncthreads();

    int r = tid;
    int b = bt0 / TOK, t0 = bt0 % TOK;
    const float* wrow; float sc = 1.f; float* obase; int ostride;
    if (r < 64) {
        wrow = wq1 + r*64; sc = 0.25f; ostride = 16;
        obase = g_q1 + ((size_t)(b*NH + (r>>4))*TOK + t0)*16 + (r&15);
    } else if (r < 128) {
        int rr = r-64; wrow = wq2 + rr*64; sc = 0.25f; ostride = 16;
        obase = g_q2 + ((size_t)(b*NH + (rr>>4))*TOK + t0)*16 + (rr&15);
    } else if (r < 192) {
        int rr = r-128; wrow = wk1 + rr*64; ostride = 16;
        obase = g_k1 + ((size_t)(b*NH + (rr>>4))*TOK + t0)*16 + (rr&15);
    } else if (r < 256) {
        int rr = r-192; wrow = wk2 + rr*64; ostride = 16;
        obase = g_k2 + ((size_t)(b*NH + (rr>>4))*TOK + t0)*16 + (rr&15);
    } else {
        int rr = r-256; wrow = wv + rr*64; ostride = 32;
        obase = g_v + ((size_t)(b*NH + (rr>>5))*TOK + t0)*32 + (rr&31);
    }
    float wr[64];
#pragma unroll
    for (int i4 = 0; i4 < 16; i4++) {
        float4 w4 = ((const float4*)wrow)[i4];
        wr[i4*4+0]=w4.x*sc; wr[i4*4+1]=w4.y*sc; wr[i4*4+2]=w4.z*sc; wr[i4*4+3]=w4.w*sc;
    }
    float acc[16];
#pragma unroll
    for (int t = 0; t < 16; t++) acc[t] = 0.f;
    for (int i = 0; i < 64; i += 4) {
#pragma unroll
        for (int t = 0; t < 16; t++) {
            float4 xv = *(const float4*)&xsh[t*64 + i];
            acc[t] += wr[i]*xv.x + wr[i+1]*xv.y + wr[i+2]*xv.z + wr[i+3]*xv.w;
        }
    }
#pragma unroll
    for (int t = 0; t < 16; t++) obase[(size_t)t*ostride] = acc[t];
}

// ---------------- attention partial: one 256-key chunk per block (R9 exact) --
__global__ __launch_bounds__(256) void attn_part_kernel() {
    extern __shared__ float smem[];
    int tid = threadIdx.x;
    int qi = tid >> 6, ql = tid & 63;
    int bxr = 104 - blockIdx.x;         // heavy (qb,chunk) first
    int qb = 0, nchw;
    for (;; qb++) { nchw = (qb >> 2) + 1; if (bxr < nchw) break; bxr -= nchw; }
    int chunk = bxr;
    int bh = blockIdx.y;
    int q = qb*64 + ql;
    int nt = qb + 1;                    // total key tiles for this qb
    int tiles = nt - chunk*4; if (tiles > 4) tiles = 4;

    const float* k1base = g_k1 + (size_t)bh*TOK*16;
    const float* k2base = g_k2 + (size_t)bh*TOK*16;
    const float* vbase  = g_v  + (size_t)bh*TOK*32;

    for (int i = tid; i < tiles*1024; i += 256) {
        int tI = i >> 10, j = i & 1023;
        int kt = chunk*4 + tI;
        float4 val;
        if (j < 256)      val = ((const float4*)(k1base + (size_t)kt*64*16))[j];
        else if (j < 512) val = ((const float4*)(k2base + (size_t)kt*64*16))[j-256];
        else              val = ((const float4*)(vbase  + (size_t)kt*64*32))[j-512];
        ((float4*)&smem[tI*4096])[j] = val;
    }

    const ulonglong2* qp1 = (const ulonglong2*)(g_q1 + ((size_t)bh*TOK + q)*16);
    const ulonglong2* qp2 = (const ulonglong2*)(g_q2 + ((size_t)bh*TOK + q)*16);
    ull q1p[8], q2p[8];
#pragma unroll
    for (int i = 0; i < 4; i++) {
        ulonglong2 a = qp1[i]; q1p[i*2] = a.x; q1p[i*2+1] = a.y;
        ulonglong2 c = qp2[i]; q2p[i*2] = c.x; q2p[i*2+1] = c.y;
    }
    ull acc1p[16], acc2p[16];
#pragma unroll
    for (int i = 0; i < 16; i++) { acc1p[i] = 0ull; acc2p[i] = 0ull; }
    float l1 = 0.f, l2 = 0.f;
    __syncthreads();

    int kt = chunk*4 + qi;
    if (kt < nt) {
        int k0 = kt*64;
        int jn = q - k0 + 1;
        if (jn > 64) jn = 64;
        const float* tb = &smem[qi*4096];
        const ull* k1s = (const ull*)tb;
        const ull* k2s = (const ull*)(tb + 1024);
        const ull* vs  = (const ull*)(tb + 2048);
        for (int j = 0; j < jn; j++) {
            const ull* kk1 = &k1s[j*8];
            ull sp1 = mul2(q1p[0], kk1[0]);
#pragma unroll
            for (int i = 1; i < 8; i++) sp1 = fma2(q1p[i], kk1[i], sp1);
            const ull* kk2 = &k2s[j*8];
            ull sp2 = mul2(q2p[0], kk2[0]);
#pragma unroll
            for (int i = 1; i < 8; i++) sp2 = fma2(q2p[i], kk2[i], sp2);
            float alo, ahi, blo, bhi;
            upk2(sp1, alo, ahi);
            upk2(sp2, blo, bhi);
            float p1 = __expf(alo + ahi);
            float p2 = __expf(blo + bhi);
            l1 += p1; l2 += p2;
            ull pp1 = pk2(p1, p1), pp2 = pk2(p2, p2);
            const ull* vv = &vs[j*16];
#pragma unroll
            for (int i = 0; i < 16; i++) {
                acc1p[i] = fma2(pp1, vv[i], acc1p[i]);
                acc2p[i] = fma2(pp2, vv[i], acc2p[i]);
            }
        }
    }

    __syncthreads();
    ull* cmb = (ull*)smem;              // overlay: [3][33][64]
    if (qi) {
#pragma unroll
        for (int i = 0; i < 16; i++) {
            cmb[(size_t)(qi-1)*2112 + i*64 + ql]      = acc1p[i];
            cmb[(size_t)(qi-1)*2112 + (16+i)*64 + ql] = acc2p[i];
        }
        cmb[(size_t)(qi-1)*2112 + 32*64 + ql] = pk2(l1, l2);
    }
    __syncthreads();
    if (qi) return;

#pragma unroll
    for (int i = 0; i < 16; i++) {
#pragma unroll
        for (int c = 0; c < 3; c++) {
            acc1p[i] = add2(acc1p[i], cmb[(size_t)c*2112 + i*64 + ql]);
            acc2p[i] = add2(acc2p[i], cmb[(size_t)c*2112 + (16+i)*64 + ql]);
        }
    }
    ull lp = pk2(l1, l2);
#pragma unroll
    for (int c = 0; c < 3; c++) lp = add2(lp, cmb[(size_t)c*2112 + 32*64 + ql]);

    ull* pb = &g_part[(size_t)((bh*27 + qb)*7 + chunk)*2112 + ql];
#pragma unroll
    for (int i = 0; i < 16; i++) {
        pb[i*64]      = acc1p[i];
        pb[(16+i)*64] = acc2p[i];
    }
    pb[32*64] = lp;
}

// ---------------- fused combine + lambda + LN + output projection ------------
__global__ __launch_bounds__(256) void comb_proj_kernel(
        const float* __restrict__ lq1, const float* __restrict__ lk1,
        const float* __restrict__ lq2, const float* __restrict__ lk2,
        const float* __restrict__ w_c) {
    __shared__ float ys[64*132];       // padded rows: 132 floats
    int tid = threadIdx.x;
    int qb = blockIdx.x, b = blockIdx.y;
    int h = tid >> 6, ql = tid & 63;
    int bh = b*NH + h;
    int nch = (qb >> 2) + 1;

    ull acc1p[16], acc2p[16];
#pragma unroll
    for (int i = 0; i < 16; i++) { acc1p[i] = 0ull; acc2p[i] = 0ull; }
    ull lp = 0ull;
    const ull* base = &g_part[(size_t)((bh*27 + qb)*7)*2112 + ql];
    for (int c = 0; c < nch; c++) {
        const ull* pc = base + (size_t)c*2112;
#pragma unroll
        for (int i = 0; i < 16; i++) {
            acc1p[i] = add2(acc1p[i], pc[i*64]);
            acc2p[i] = add2(acc2p[i], pc[(16+i)*64]);
        }
        lp = add2(lp, pc[32*64]);
    }
    float l1, l2; upk2(lp, l1, l2);

    float acc1[32], acc2[32];
#pragma unroll
    for (int i = 0; i < 16; i++) {
        upk2(acc1p[i], acc1[i*2], acc1[i*2+1]);
        upk2(acc2p[i], acc2[i*2], acc2[i*2+1]);
    }

    float s1 = 0.f, s2 = 0.f;
#pragma unroll
    for (int i = 0; i < 16; i++) {
        s1 += lq1[h*16+i]*lk1[h*16+i];
        s2 += lq2[h*16+i]*lk2[h*16+i];
    }
    float lam = expf(s1) - expf(s2) + LAMBDA_INIT;
    float inv1 = 1.0f/l1, inv2 = 1.0f/l2;

    float y[32], mu = 0.f;
#pragma unroll
    for (int d = 0; d < 32; d++) {
        y[d] = acc1[d]*inv1 - lam*(acc2[d]*inv2);
        mu += y[d];
    }
    mu *= (1.0f/32.0f);
    float var = 0.f;
#pragma unroll
    for (int d = 0; d < 32; d++) { float t = y[d]-mu; var += t*t; }
    var *= (1.0f/32.0f);
    float scl = rsqrtf(var + EPS) * ONE_MINUS_LAMBDA;

    float* yp = &ys[ql*132 + h*32];
#pragma unroll
    for (int d4 = 0; d4 < 8; d4++) {
        float4 o;
        o.x = (y[d4*4+0]-mu)*scl; o.y = (y[d4*4+1]-mu)*scl;
        o.z = (y[d4*4+2]-mu)*scl; o.w = (y[d4*4+3]-mu)*scl;
        ((float4*)yp)[d4] = o;
    }
    __syncthreads();

    // phase 2: projection. thread = (tg 0..3, oc 0..63), 16 tokens each.
    int oc = tid & 63;
    int tg = tid >> 6;
    float acc[16];
#pragma unroll
    for (int t = 0; t < 16; t++) acc[t] = 0.f;
    for (int i = 0; i < 128; i += 4) {
        float4 w4 = *(const float4*)&w_c[oc*128 + i];
#pragma unroll
        for (int t = 0; t < 16; t++) {
            float4 xv = *(const float4*)&ys[(tg*16 + t)*132 + i];
            acc[t] += w4.x*xv.x + w4.y*xv.y + w4.z*xv.z + w4.w*xv.w;
        }
    }
    float* ob = g_a1 + ((size_t)(b*TOK + qb*64 + tg*16))*64 + oc;
#pragma unroll
    for (int t = 0; t < 16; t++) ob[(size_t)t*64] = acc[t];
}

// ---------------- 3D conv 64->256: single-load weights, (dz,dy)->ly order ----
__global__ __launch_bounds__(128) void conv_kernel(const float* __restrict__ b_conv) {
    __shared__ float sin[64*3*4*16];   // [ic][dz][ry][16]
    int tid = threadIdx.x;
    int zyg = blockIdx.x;              // 12*6
    int b = blockIdx.y;
    int z = zyg / 6, y0 = (zyg % 6) * 2;

    for (int R = tid; R < 768; R += 128) {
        int ic = R / 12, rem = R % 12;
        int dz = rem >> 2, ry = rem & 3;
        int zz = z + dz - 1, yy = y0 + ry - 1;
        float* dst = &sin[R*16];
        if (zz < 0 || zz >= 12 || yy < 0 || yy >= 12) {
#pragma unroll
            for (int i = 0; i < 16; i++) dst[i] = 0.f;
        } else {
            const float* src = g_a1 + (size_t)b*110592 + ic*1728 + zz*144 + yy*12;
            dst[0] = 0.f;
#pragma unroll
            for (int i = 0; i < 12; i++) dst[1+i] = src[i];
            dst[13] = 0.f; dst[14] = 0.f; dst[15] = 0.f;
        }
    }
    __syncthreads();

    int t = tid;                       // oc pair (t, t+128)
    ull accp[2][12];
#pragma unroll
    for (int ly = 0; ly < 2; ly++)
#pragma unroll
        for (int x = 0; x < 12; x++) accp[ly][x] = 0ull;

    for (int ic = 0; ic < 64; ic++) {
#pragma unroll
        for (int dz = 0; dz < 3; dz++) {
            const float* rbase = &sin[((ic*3 + dz)*4)*16];
#pragma unroll
            for (int dy = 0; dy < 3; dy++) {
                int tap = ic*9 + dz*3 + dy;
                ulonglong2 w01 = g_wtA[(size_t)tap*128 + t];   // coalesced 16B
                ull        w2  = g_wtB[(size_t)tap*128 + t];   // coalesced 8B
#pragma unroll
                for (int ly = 0; ly < 2; ly++) {
                    int r = dy + ly;   // input row index 0..3, compile-time
                    const float4* v4 = (const float4*)&rbase[r*16];
                    float4 a = v4[0], bb = v4[1], c = v4[2], d = v4[3];
                    float v[16] = {a.x,a.y,a.z,a.w, bb.x,bb.y,bb.z,bb.w,
                                   c.x,c.y,c.z,c.w, d.x,d.y,d.z,d.w};
                    ull vb[14];
#pragma unroll
                    for (int x = 0; x < 14; x++) vb[x] = pk2(v[x], v[x]);
#pragma unroll
                    for (int x = 0; x < 12; x++) {
                        accp[ly][x] = fma2(w01.x, vb[x],   accp[ly][x]);
                        accp[ly][x] = fma2(w01.y, vb[x+1], accp[ly][x]);
                        accp[ly][x] = fma2(w2,    vb[x+2], accp[ly][x]);
                    }
                }
            }
        }
    }

    float bias0 = b_conv[t], bias1 = b_conv[t+128];
    float ps0 = 0.f, ps1 = 0.f;        // pool partials (bias included)
#pragma unroll
    for (int ly = 0; ly < 2; ly++) {
        float r0[12], r1[12];
#pragma unroll
        for (int x = 0; x < 12; x++) {
            float lo, hi; upk2(accp[ly][x], lo, hi);
            r0[x] = lo + bias0; r1[x] = hi + bias1;
            ps0 += r0[x];      ps1 += r1[x];
        }
        float* op0 = g_y1 + ((size_t)b*256 + t)*1728 + z*144 + (y0+ly)*12;
        float* op1 = g_y1 + ((size_t)b*256 + t + 128)*1728 + z*144 + (y0+ly)*12;
#pragma unroll
        for (int x4 = 0; x4 < 3; x4++) {
            ((float4*)op0)[x4] = make_float4(r0[x4*4], r0[x4*4+1], r0[x4*4+2], r0[x4*4+3]);
            ((float4*)op1)[x4] = make_float4(r1[x4*4], r1[x4*4+1], r1[x4*4+2], r1[x4*4+3]);
        }
    }
    g_cp[((size_t)b*72 + zyg)*256 + t]       = ps0;
    g_cp[((size_t)b*72 + zyg)*256 + t + 128] = ps1;
}

// ---------------- channel pooling ----------------
__global__ __launch_bounds__(128) void pool_kernel() {
    int ch = blockIdx.x & 511;
    int b = blockIdx.x >> 9;
    int tid = threadIdx.x;
    float s = 0.f;
    if (ch < 256) {
        if (tid < 72) s = g_cp[((size_t)b*72 + tid)*256 + ch];
    } else {
        const float* src;
        if (ch < 448) src = g_y2 + ((size_t)b*192 + (ch-256))*SP;
        else          src = g_low + ((size_t)b*64 + (ch-448))*SP;
        for (int i = tid; i < SP; i += 128) s += src[i];
    }
#pragma unroll
    for (int off = 16; off > 0; off >>= 1)
        s += __shfl_down_sync(0xffffffffu, s, off);
    __shared__ float red[4];
    if ((tid & 31) == 0) red[tid >> 5] = s;
    __syncthreads();
    if (tid == 0)
        g_pool[blockIdx.x] = (red[0]+red[1]+red[2]+red[3]) * (1.0f/SP);
}

// ---------------- softmax over 512 channels ----------------
__global__ __launch_bounds__(512) void smx_kernel() {
    __shared__ float sm[512];
    int b = blockIdx.x, tid = threadIdx.x;
    float p = g_pool[b*512 + tid];
    sm[tid] = p;
    __syncthreads();
    for (int off = 256; off > 0; off >>= 1) {
        if (tid < off) sm[tid] = fmaxf(sm[tid], sm[tid+off]);
        __syncthreads();
    }
    float mx = sm[0];
    __syncthreads();
    float e = expf(p - mx);
    sm[tid] = e;
    __syncthreads();
    for (int off = 256; off > 0; off >>= 1) {
        if (tid < off) sm[tid] += sm[tid+off];
        __syncthreads();
    }
    g_smx[b*512 + tid] = e / sm[0];
}

// ---------------- final gate + fold ----------------
__global__ __launch_bounds__(256) void final_kernel(float* __restrict__ out) {
    int i = blockIdx.x * 256 + threadIdx.x;   // over 4*256*1728
    int s = i % SP;
    int c = (i / SP) & 255;
    int b = i / (SP*256);
    float v1 = g_y1[i];
    float w1 = g_smx[b*512 + c];
    float v2, w2 = g_smx[b*512 + 256 + c];
    if (c < 192) v2 = g_y2[((size_t)b*192 + c)*SP + s];
    else         v2 = g_low[((size_t)b*64 + (c-192))*SP + s];
    out[i] = w1*v1 + w2*v2;
}

// ---------------- launch ----------------
extern "C" void kernel_launch(void* const* d_in, const int* in_sizes, int n_in,
                              void* d_out, int out_size) {
    const float* x      = (const float*)d_in[0];
    const float* w_sq1  = (const float*)d_in[1];
    const float* w_sq2  = (const float*)d_in[2];
    const float* w_pwc2 = (const float*)d_in[3];
    const float* w_conv = (const float*)d_in[4];
    const float* b_conv = (const float*)d_in[5];
    const float* w_q1   = (const float*)d_in[6];
    const float* w_q2   = (const float*)d_in[7];
    const float* w_k1   = (const float*)d_in[8];
    const float* w_k2   = (const float*)d_in[9];
    const float* w_v    = (const float*)d_in[10];
    const float* w_c    = (const float*)d_in[11];
    const float* lq1    = (const float*)d_in[12];
    const float* lk1    = (const float*)d_in[13];
    const float* lq2    = (const float*)d_in[14];
    const float* lk2    = (const float*)d_in[15];
    float* out = (float*)d_out;

    cudaFuncSetAttribute(attn_part_kernel,
                         cudaFuncAttributeMaxDynamicSharedMemorySize, 65536);

    prep_kernel<<<960, 192>>>(x, w_sq1, w_sq2, w_conv);
    qkv_kernel<<<432, 384>>>(w_q1, w_q2, w_k1, w_k2, w_v);
    pw_kernel<<<dim3(4,24,9), 192>>>(w_pwc2);
    attn_part_kernel<<<dim3(105,16), 256, 65536>>>();
    comb_proj_kernel<<<dim3(27,4), 256>>>(lq1, lk1, lq2, lk2, w_c);
    conv_kernel<<<dim3(72,4), 128>>>(b_conv);
    pool_kernel<<<2048, 128>>>();
    smx_kernel<<<4, 512>>>();
    final_kernel<<<6912, 256>>>(out);
}

// round 16
// speedup vs baseline: 1.0672x; 1.0039x over previous
#include <cuda_runtime.h>
#include <math.h>

#define SP   1728
#define TOK  1728
#define BATCH 4
#define NH   4
#define LAMBDA_INIT 0.55605820416f
#define ONE_MINUS_LAMBDA 0.44394179584f
#define EPS 1e-5f

typedef unsigned long long ull;

// ---------------- packed f32x2 helpers ----------------
__device__ __forceinline__ ull pk2(float lo, float hi) {
    ull r; asm("mov.b64 %0,{%1,%2};" : "=l"(r) : "f"(lo), "f"(hi)); return r;
}
__device__ __forceinline__ void upk2(ull v, float& lo, float& hi) {
    asm("mov.b64 {%0,%1},%2;" : "=f"(lo), "=f"(hi) : "l"(v));
}
__device__ __forceinline__ ull fma2(ull a, ull b, ull c) {
    ull d; asm("fma.rn.f32x2 %0,%1,%2,%3;" : "=l"(d) : "l"(a), "l"(b), "l"(c)); return d;
}
__device__ __forceinline__ ull mul2(ull a, ull b) {
    ull d; asm("mul.rn.f32x2 %0,%1,%2;" : "=l"(d) : "l"(a), "l"(b)); return d;
}
__device__ __forceinline__ ull add2(ull a, ull b) {
    ull d; asm("add.rn.f32x2 %0,%1,%2;" : "=l"(d) : "l"(a), "l"(b)); return d;
}

// ---------------- device scratch ----------------
__device__ float g_up  [BATCH*64*SP];
__device__ float g_low [BATCH*64*SP];
__device__ float g_q1  [BATCH*NH*TOK*16];
__device__ float g_q2  [BATCH*NH*TOK*16];
__device__ float g_k1  [BATCH*NH*TOK*16];
__device__ float g_k2  [BATCH*NH*TOK*16];
__device__ float g_v   [BATCH*NH*TOK*32];
__device__ ull   g_part[16*27*7*33*64];   // [bh][qb][chunk][elem33][q64]
__device__ float g_a1  [BATCH*TOK*64];    // == (B,64,12,12,12) raw reshape
__device__ float g_y1  [BATCH*256*SP];
__device__ float g_y2  [BATCH*192*SP];
__device__ ulonglong2 g_wtA[64*9*128];    // taps 0,1 packed (oc=t, oc=t+128), dense
__device__ ull        g_wtB[64*9*128];    // tap 2 packed, dense
__device__ float g_cp  [BATCH*72*256];    // conv per-block channel partial sums
__device__ float g_pool[BATCH*512];
__device__ float g_smx [BATCH*512];

// ---------------- side stream + events (created at static init) -------------
static cudaStream_t g_s1;
static cudaEvent_t  g_evF, g_evWL, g_evS1;
namespace {
struct StreamInit {
    StreamInit() {
        cudaStreamCreateWithFlags(&g_s1, cudaStreamNonBlocking);
        cudaEventCreateWithFlags(&g_evF,  cudaEventDisableTiming);
        cudaEventCreateWithFlags(&g_evWL, cudaEventDisableTiming);
        cudaEventCreateWithFlags(&g_evS1, cudaEventDisableTiming);
    }
};
StreamInit g_streamInit;
}

// ---------------- pw0: x upper half -> g_up (critical path) -----------------
__global__ __launch_bounds__(192) void pw0_kernel(
        const float* __restrict__ x, const float* __restrict__ w_sq1) {
    __shared__ ull wsh2[4*128];
    int i = blockIdx.x;
    int tid = threadIdx.x;
    int b = i & 3; i >>= 2;
    int og = i & 7; i >>= 3;
    int zc = i;                          // 0..8
    for (int ii = tid; ii < 4*128; ii += 192) {
        int p = ii >> 7, c = ii & 127;
        wsh2[ii] = pk2(w_sq1[(size_t)(og*8 + 2*p)*128 + c],
                       w_sq1[(size_t)(og*8 + 2*p + 1)*128 + c]);
    }
    __syncthreads();
    const float* inb = x + (size_t)b*256*SP;
    float* outb = g_up + (size_t)b*64*SP + (size_t)og*8*SP;
    int s = zc*192 + tid;
    ull acc[4];
#pragma unroll
    for (int p = 0; p < 4; p++) acc[p] = 0ull;
    for (int i2 = 0; i2 < 128; i2 += 4) {
        ull xp0 = pk2(inb[(i2+0)*SP + s], inb[(i2+0)*SP + s]);
        ull xp1 = pk2(inb[(i2+1)*SP + s], inb[(i2+1)*SP + s]);
        ull xp2 = pk2(inb[(i2+2)*SP + s], inb[(i2+2)*SP + s]);
        ull xp3 = pk2(inb[(i2+3)*SP + s], inb[(i2+3)*SP + s]);
#pragma unroll
        for (int p = 0; p < 4; p++) {
            ulonglong2 wa = *(const ulonglong2*)&wsh2[p*128 + i2];
            ulonglong2 wb = *(const ulonglong2*)&wsh2[p*128 + i2 + 2];
            acc[p] = fma2(wa.x, xp0, acc[p]);
            acc[p] = fma2(wa.y, xp1, acc[p]);
            acc[p] = fma2(wb.x, xp2, acc[p]);
            acc[p] = fma2(wb.y, xp3, acc[p]);
        }
    }
#pragma unroll
    for (int p = 0; p < 4; p++) {
        float lo, hi; upk2(acc[p], lo, hi);
        outb[(2*p)*SP + s]   = lo;
        outb[(2*p+1)*SP + s] = hi;
    }
}

// ---------------- wl: pw1 (x lower -> g_low) + conv weight transpose --------
// bx [0,288): pw1; bx [288,672): wtrans
__global__ __launch_bounds__(192) void wl_kernel(
        const float* __restrict__ x, const float* __restrict__ w_sq2,
        const float* __restrict__ w_conv) {
    __shared__ ull wsh2[4*128];
    int bx = blockIdx.x;
    int tid = threadIdx.x;
    if (bx < 288) {
        int i = bx;
        int b = i & 3; i >>= 2;
        int og = i & 7; i >>= 3;
        int zc = i;                          // 0..8
        for (int ii = tid; ii < 4*128; ii += 192) {
            int p = ii >> 7, c = ii & 127;
            wsh2[ii] = pk2(w_sq2[(size_t)(og*8 + 2*p)*128 + c],
                           w_sq2[(size_t)(og*8 + 2*p + 1)*128 + c]);
        }
        __syncthreads();
        const float* inb = x + (size_t)b*256*SP + (size_t)128*SP;
        float* outb = g_low + (size_t)b*64*SP + (size_t)og*8*SP;
        int s = zc*192 + tid;
        ull acc[4];
#pragma unroll
        for (int p = 0; p < 4; p++) acc[p] = 0ull;
        for (int i2 = 0; i2 < 128; i2 += 4) {
            ull xp0 = pk2(inb[(i2+0)*SP + s], inb[(i2+0)*SP + s]);
            ull xp1 = pk2(inb[(i2+1)*SP + s], inb[(i2+1)*SP + s]);
            ull xp2 = pk2(inb[(i2+2)*SP + s], inb[(i2+2)*SP + s]);
            ull xp3 = pk2(inb[(i2+3)*SP + s], inb[(i2+3)*SP + s]);
#pragma unroll
            for (int p = 0; p < 4; p++) {
                ulonglong2 wa = *(const ulonglong2*)&wsh2[p*128 + i2];
                ulonglong2 wb = *(const ulonglong2*)&wsh2[p*128 + i2 + 2];
                acc[p] = fma2(wa.x, xp0, acc[p]);
                acc[p] = fma2(wa.y, xp1, acc[p]);
                acc[p] = fma2(wb.x, xp2, acc[p]);
                acc[p] = fma2(wb.y, xp3, acc[p]);
            }
        }
#pragma unroll
        for (int p = 0; p < 4; p++) {
            float lo, hi; upk2(acc[p], lo, hi);
            outb[(2*p)*SP + s]   = lo;
            outb[(2*p+1)*SP + s] = hi;
        }
    } else {
        int idx = (bx - 288)*192 + tid;      // < 64*9*128
        int t = idx & 127;
        int icr = idx >> 7;                  // ic*9 + r
        int ic = icr / 9, r = icr % 9;
        const float* s0 = w_conv + (size_t)t*1728 + ic*27 + r*3;
        const float* s1 = w_conv + (size_t)(t+128)*1728 + ic*27 + r*3;
        ulonglong2 w01;
        w01.x = pk2(s0[0], s1[0]);
        w01.y = pk2(s0[1], s1[1]);
        g_wtA[idx] = w01;
        g_wtB[idx] = pk2(s0[2], s1[2]);
    }
}

// ---------------- pointwise conv (mode 2 only: g_low -> g_y2, NI=64) --------
__global__ __launch_bounds__(192) void pw_kernel(const float* __restrict__ w) {
    __shared__ ull wsh2[4*64];
    int b = blockIdx.x, og = blockIdx.y, tid = threadIdx.x;
    for (int i = tid; i < 4*64; i += 192) {
        int p = i >> 6, c = i & 63;
        wsh2[i] = pk2(w[(size_t)(og*8 + 2*p)*64 + c],
                      w[(size_t)(og*8 + 2*p + 1)*64 + c]);
    }
    __syncthreads();
    const float* inb = g_low + (size_t)b*64*SP;
    float* outb = g_y2 + (size_t)b*192*SP + (size_t)og*8*SP;
    int s = blockIdx.z*192 + tid;
    ull acc[4];
#pragma unroll
    for (int p = 0; p < 4; p++) acc[p] = 0ull;
    for (int i = 0; i < 64; i += 4) {
        ull xp0 = pk2(inb[(i+0)*SP + s], inb[(i+0)*SP + s]);
        ull xp1 = pk2(inb[(i+1)*SP + s], inb[(i+1)*SP + s]);
        ull xp2 = pk2(inb[(i+2)*SP + s], inb[(i+2)*SP + s]);
        ull xp3 = pk2(inb[(i+3)*SP + s], inb[(i+3)*SP + s]);
#pragma unroll
        for (int p = 0; p < 4; p++) {
            ulonglong2 wa = *(const ulonglong2*)&wsh2[p*64 + i];
            ulonglong2 wb = *(const ulonglong2*)&wsh2[p*64 + i + 2];
            acc[p] = fma2(wa.x, xp0, acc[p]);
            acc[p] = fma2(wa.y, xp1, acc[p]);
            acc[p] = fma2(wb.x, xp2, acc[p]);
            acc[p] = fma2(wb.y, xp3, acc[p]);
        }
    }
#pragma unroll
    for (int p = 0; p < 4; p++) {
        float lo, hi; upk2(acc[p], lo, hi);
        outb[(2*p)*SP + s]   = lo;
        outb[(2*p+1)*SP + s] = hi;
    }
}

// ---------------- QKV projection (g_up raw-reshaped to (B*T,64)) -------------
__global__ __launch_bounds__(384) void qkv_kernel(
        const float* __restrict__ wq1, const float* __restrict__ wq2,
        const float* __restrict__ wk1, const float* __restrict__ wk2,
        const float* __restrict__ wv) {
    __shared__ float xsh[16*64];
    int tid = threadIdx.x;
    int bt0 = blockIdx.x * 16;
    if (tid < 256) ((float4*)xsh)[tid] = ((const float4*)g_up)[bt0*16 + tid];
    __syncthreads();

    int r = tid;
    int b = bt0 / TOK, t0 = bt0 % TOK;
    const float* wrow; float sc = 1.f; float* obase; int ostride;
    if (r < 64) {
        wrow = wq1 + r*64; sc = 0.25f; ostride = 16;
        obase = g_q1 + ((size_t)(b*NH + (r>>4))*TOK + t0)*16 + (r&15);
    } else if (r < 128) {
        int rr = r-64; wrow = wq2 + rr*64; sc = 0.25f; ostride = 16;
        obase = g_q2 + ((size_t)(b*NH + (rr>>4))*TOK + t0)*16 + (rr&15);
    } else if (r < 192) {
        int rr = r-128; wrow = wk1 + rr*64; ostride = 16;
        obase = g_k1 + ((size_t)(b*NH + (rr>>4))*TOK + t0)*16 + (rr&15);
    } else if (r < 256) {
        int rr = r-192; wrow = wk2 + rr*64; ostride = 16;
        obase = g_k2 + ((size_t)(b*NH + (rr>>4))*TOK + t0)*16 + (rr&15);
    } else {
        int rr = r-256; wrow = wv + rr*64; ostride = 32;
        obase = g_v + ((size_t)(b*NH + (rr>>5))*TOK + t0)*32 + (rr&31);
    }
    float wr[64];
#pragma unroll
    for (int i4 = 0; i4 < 16; i4++) {
        float4 w4 = ((const float4*)wrow)[i4];
        wr[i4*4+0]=w4.x*sc; wr[i4*4+1]=w4.y*sc; wr[i4*4+2]=w4.z*sc; wr[i4*4+3]=w4.w*sc;
    }
    float acc[16];
#pragma unroll
    for (int t = 0; t < 16; t++) acc[t] = 0.f;
    for (int i = 0; i < 64; i += 4) {
#pragma unroll
        for (int t = 0; t < 16; t++) {
            float4 xv = *(const float4*)&xsh[t*64 + i];
            acc[t] += wr[i]*xv.x + wr[i+1]*xv.y + wr[i+2]*xv.z + wr[i+3]*xv.w;
        }
    }
#pragma unroll
    for (int t = 0; t < 16; t++) obase[(size_t)t*ostride] = acc[t];
}

// ---------------- attention partial: one 256-key chunk per block (R9 exact) --
__global__ __launch_bounds__(256) void attn_part_kernel() {
    extern __shared__ float smem[];
    int tid = threadIdx.x;
    int qi = tid >> 6, ql = tid & 63;
    int bxr = 104 - blockIdx.x;         // heavy (qb,chunk) first
    int qb = 0, nchw;
    for (;; qb++) { nchw = (qb >> 2) + 1; if (bxr < nchw) break; bxr -= nchw; }
    int chunk = bxr;
    int bh = blockIdx.y;
    int q = qb*64 + ql;
    int nt = qb + 1;                    // total key tiles for this qb
    int tiles = nt - chunk*4; if (tiles > 4) tiles = 4;

    const float* k1base = g_k1 + (size_t)bh*TOK*16;
    const float* k2base = g_k2 + (size_t)bh*TOK*16;
    const float* vbase  = g_v  + (size_t)bh*TOK*32;

    for (int i = tid; i < tiles*1024; i += 256) {
        int tI = i >> 10, j = i & 1023;
        int kt = chunk*4 + tI;
        float4 val;
        if (j < 256)      val = ((const float4*)(k1base + (size_t)kt*64*16))[j];
        else if (j < 512) val = ((const float4*)(k2base + (size_t)kt*64*16))[j-256];
        else              val = ((const float4*)(vbase  + (size_t)kt*64*32))[j-512];
        ((float4*)&smem[tI*4096])[j] = val;
    }

    const ulonglong2* qp1 = (const ulonglong2*)(g_q1 + ((size_t)bh*TOK + q)*16);
    const ulonglong2* qp2 = (const ulonglong2*)(g_q2 + ((size_t)bh*TOK + q)*16);
    ull q1p[8], q2p[8];
#pragma unroll
    for (int i = 0; i < 4; i++) {
        ulonglong2 a = qp1[i]; q1p[i*2] = a.x; q1p[i*2+1] = a.y;
        ulonglong2 c = qp2[i]; q2p[i*2] = c.x; q2p[i*2+1] = c.y;
    }
    ull acc1p[16], acc2p[16];
#pragma unroll
    for (int i = 0; i < 16; i++) { acc1p[i] = 0ull; acc2p[i] = 0ull; }
    float l1 = 0.f, l2 = 0.f;
    __syncthreads();

    int kt = chunk*4 + qi;
    if (kt < nt) {
        int k0 = kt*64;
        int jn = q - k0 + 1;
        if (jn > 64) jn = 64;
        const float* tb = &smem[qi*4096];
        const ull* k1s = (const ull*)tb;
        const ull* k2s = (const ull*)(tb + 1024);
        const ull* vs  = (const ull*)(tb + 2048);
        for (int j = 0; j < jn; j++) {
            const ull* kk1 = &k1s[j*8];
            ull sp1 = mul2(q1p[0], kk1[0]);
#pragma unroll
            for (int i = 1; i < 8; i++) sp1 = fma2(q1p[i], kk1[i], sp1);
            const ull* kk2 = &k2s[j*8];
            ull sp2 = mul2(q2p[0], kk2[0]);
#pragma unroll
            for (int i = 1; i < 8; i++) sp2 = fma2(q2p[i], kk2[i], sp2);
            float alo, ahi, blo, bhi;
            upk2(sp1, alo, ahi);
            upk2(sp2, blo, bhi);
            float p1 = __expf(alo + ahi);
            float p2 = __expf(blo + bhi);
            l1 += p1; l2 += p2;
            ull pp1 = pk2(p1, p1), pp2 = pk2(p2, p2);
            const ull* vv = &vs[j*16];
#pragma unroll
            for (int i = 0; i < 16; i++) {
                acc1p[i] = fma2(pp1, vv[i], acc1p[i]);
                acc2p[i] = fma2(pp2, vv[i], acc2p[i]);
            }
        }
    }

    __syncthreads();
    ull* cmb = (ull*)smem;              // overlay: [3][33][64]
    if (qi) {
#pragma unroll
        for (int i = 0; i < 16; i++) {
            cmb[(size_t)(qi-1)*2112 + i*64 + ql]      = acc1p[i];
            cmb[(size_t)(qi-1)*2112 + (16+i)*64 + ql] = acc2p[i];
        }
        cmb[(size_t)(qi-1)*2112 + 32*64 + ql] = pk2(l1, l2);
    }
    __syncthreads();
    if (qi) return;

#pragma unroll
    for (int i = 0; i < 16; i++) {
#pragma unroll
        for (int c = 0; c < 3; c++) {
            acc1p[i] = add2(acc1p[i], cmb[(size_t)c*2112 + i*64 + ql]);
            acc2p[i] = add2(acc2p[i], cmb[(size_t)c*2112 + (16+i)*64 + ql]);
        }
    }
    ull lp = pk2(l1, l2);
#pragma unroll
    for (int c = 0; c < 3; c++) lp = add2(lp, cmb[(size_t)c*2112 + 32*64 + ql]);

    ull* pb = &g_part[(size_t)((bh*27 + qb)*7 + chunk)*2112 + ql];
#pragma unroll
    for (int i = 0; i < 16; i++) {
        pb[i*64]      = acc1p[i];
        pb[(16+i)*64] = acc2p[i];
    }
    pb[32*64] = lp;
}

// ---------------- fused combine + lambda + LN + output projection ------------
__global__ __launch_bounds__(256) void comb_proj_kernel(
        const float* __restrict__ lq1, const float* __restrict__ lk1,
        const float* __restrict__ lq2, const float* __restrict__ lk2,
        const float* __restrict__ w_c) {
    __shared__ float ys[64*132];       // padded rows: 132 floats
    int tid = threadIdx.x;
    int qb = blockIdx.x, b = blockIdx.y;
    int h = tid >> 6, ql = tid & 63;
    int bh = b*NH + h;
    int nch = (qb >> 2) + 1;

    ull acc1p[16], acc2p[16];
#pragma unroll
    for (int i = 0; i < 16; i++) { acc1p[i] = 0ull; acc2p[i] = 0ull; }
    ull lp = 0ull;
    const ull* base = &g_part[(size_t)((bh*27 + qb)*7)*2112 + ql];
    for (int c = 0; c < nch; c++) {
        const ull* pc = base + (size_t)c*2112;
#pragma unroll
        for (int i = 0; i < 16; i++) {
            acc1p[i] = add2(acc1p[i], pc[i*64]);
            acc2p[i] = add2(acc2p[i], pc[(16+i)*64]);
        }
        lp = add2(lp, pc[32*64]);
    }
    float l1, l2; upk2(lp, l1, l2);

    float acc1[32], acc2[32];
#pragma unroll
    for (int i = 0; i < 16; i++) {
        upk2(acc1p[i], acc1[i*2], acc1[i*2+1]);
        upk2(acc2p[i], acc2[i*2], acc2[i*2+1]);
    }

    float s1 = 0.f, s2 = 0.f;
#pragma unroll
    for (int i = 0; i < 16; i++) {
        s1 += lq1[h*16+i]*lk1[h*16+i];
        s2 += lq2[h*16+i]*lk2[h*16+i];
    }
    float lam = expf(s1) - expf(s2) + LAMBDA_INIT;
    float inv1 = 1.0f/l1, inv2 = 1.0f/l2;

    float y[32], mu = 0.f;
#pragma unroll
    for (int d = 0; d < 32; d++) {
        y[d] = acc1[d]*inv1 - lam*(acc2[d]*inv2);
        mu += y[d];
    }
    mu *= (1.0f/32.0f);
    float var = 0.f;
#pragma unroll
    for (int d = 0; d < 32; d++) { float t = y[d]-mu; var += t*t; }
    var *= (1.0f/32.0f);
    float scl = rsqrtf(var + EPS) * ONE_MINUS_LAMBDA;

    float* yp = &ys[ql*132 + h*32];
#pragma unroll
    for (int d4 = 0; d4 < 8; d4++) {
        float4 o;
        o.x = (y[d4*4+0]-mu)*scl; o.y = (y[d4*4+1]-mu)*scl;
        o.z = (y[d4*4+2]-mu)*scl; o.w = (y[d4*4+3]-mu)*scl;
        ((float4*)yp)[d4] = o;
    }
    __syncthreads();

    // phase 2: projection. thread = (tg 0..3, oc 0..63), 16 tokens each.
    int oc = tid & 63;
    int tg = tid >> 6;
    float acc[16];
#pragma unroll
    for (int t = 0; t < 16; t++) acc[t] = 0.f;
    for (int i = 0; i < 128; i += 4) {
        float4 w4 = *(const float4*)&w_c[oc*128 + i];
#pragma unroll
        for (int t = 0; t < 16; t++) {
            float4 xv = *(const float4*)&ys[(tg*16 + t)*132 + i];
            acc[t] += w4.x*xv.x + w4.y*xv.y + w4.z*xv.z + w4.w*xv.w;
        }
    }
    float* ob = g_a1 + ((size_t)(b*TOK + qb*64 + tg*16))*64 + oc;
#pragma unroll
    for (int t = 0; t < 16; t++) ob[(size_t)t*64] = acc[t];
}

// ---------------- 3D conv 64->256: single-load weights, (dz,dy)->ly order ----
__global__ __launch_bounds__(128) void conv_kernel(const float* __restrict__ b_conv) {
    __shared__ float sin[64*3*4*16];   // [ic][dz][ry][16]
    int tid = threadIdx.x;
    int zyg = blockIdx.x;              // 12*6
    int b = blockIdx.y;
    int z = zyg / 6, y0 = (zyg % 6) * 2;

    for (int R = tid; R < 768; R += 128) {
        int ic = R / 12, rem = R % 12;
        int dz = rem >> 2, ry = rem & 3;
        int zz = z + dz - 1, yy = y0 + ry - 1;
        float* dst = &sin[R*16];
        if (zz < 0 || zz >= 12 || yy < 0 || yy >= 12) {
#pragma unroll
            for (int i = 0; i < 16; i++) dst[i] = 0.f;
        } else {
            const float* src = g_a1 + (size_t)b*110592 + ic*1728 + zz*144 + yy*12;
            dst[0] = 0.f;
#pragma unroll
            for (int i = 0; i < 12; i++) dst[1+i] = src[i];
            dst[13] = 0.f; dst[14] = 0.f; dst[15] = 0.f;
        }
    }
    __syncthreads();

    int t = tid;                       // oc pair (t, t+128)
    ull accp[2][12];
#pragma unroll
    for (int ly = 0; ly < 2; ly++)
#pragma unroll
        for (int x = 0; x < 12; x++) accp[ly][x] = 0ull;

    for (int ic = 0; ic < 64; ic++) {
#pragma unroll
        for (int dz = 0; dz < 3; dz++) {
            const float* rbase = &sin[((ic*3 + dz)*4)*16];
#pragma unroll
            for (int dy = 0; dy < 3; dy++) {
                int tap = ic*9 + dz*3 + dy;
                ulonglong2 w01 = g_wtA[(size_t)tap*128 + t];   // coalesced 16B
                ull        w2  = g_wtB[(size_t)tap*128 + t];   // coalesced 8B
#pragma unroll
                for (int ly = 0; ly < 2; ly++) {
                    int r = dy + ly;   // input row index 0..3, compile-time
                    const float4* v4 = (const float4*)&rbase[r*16];
                    float4 a = v4[0], bb = v4[1], c = v4[2], d = v4[3];
                    float v[16] = {a.x,a.y,a.z,a.w, bb.x,bb.y,bb.z,bb.w,
                                   c.x,c.y,c.z,c.w, d.x,d.y,d.z,d.w};
                    ull vb[14];
#pragma unroll
                    for (int x = 0; x < 14; x++) vb[x] = pk2(v[x], v[x]);
#pragma unroll
                    for (int x = 0; x < 12; x++) {
                        accp[ly][x] = fma2(w01.x, vb[x],   accp[ly][x]);
                        accp[ly][x] = fma2(w01.y, vb[x+1], accp[ly][x]);
                        accp[ly][x] = fma2(w2,    vb[x+2], accp[ly][x]);
                    }
                }
            }
        }
    }

    float bias0 = b_conv[t], bias1 = b_conv[t+128];
    float ps0 = 0.f, ps1 = 0.f;        // pool partials (bias included)
#pragma unroll
    for (int ly = 0; ly < 2; ly++) {
        float r0[12], r1[12];
#pragma unroll
        for (int x = 0; x < 12; x++) {
            float lo, hi; upk2(accp[ly][x], lo, hi);
            r0[x] = lo + bias0; r1[x] = hi + bias1;
            ps0 += r0[x];      ps1 += r1[x];
        }
        float* op0 = g_y1 + ((size_t)b*256 + t)*1728 + z*144 + (y0+ly)*12;
        float* op1 = g_y1 + ((size_t)b*256 + t + 128)*1728 + z*144 + (y0+ly)*12;
#pragma unroll
        for (int x4 = 0; x4 < 3; x4++) {
            ((float4*)op0)[x4] = make_float4(r0[x4*4], r0[x4*4+1], r0[x4*4+2], r0[x4*4+3]);
            ((float4*)op1)[x4] = make_float4(r1[x4*4], r1[x4*4+1], r1[x4*4+2], r1[x4*4+3]);
        }
    }
    g_cp[((size_t)b*72 + zyg)*256 + t]       = ps0;
    g_cp[((size_t)b*72 + zyg)*256 + t + 128] = ps1;
}

// ---------------- channel pooling: y1 half (g_cp reduce) ----------------
__global__ __launch_bounds__(128) void pool_y1_kernel() {
    int ch = blockIdx.x & 255;
    int b = blockIdx.x >> 8;
    int tid = threadIdx.x;
    float s = 0.f;
    if (tid < 72) s = g_cp[((size_t)b*72 + tid)*256 + ch];
#pragma unroll
    for (int off = 16; off > 0; off >>= 1)
        s += __shfl_down_sync(0xffffffffu, s, off);
    __shared__ float red[4];
    if ((tid & 31) == 0) red[tid >> 5] = s;
    __syncthreads();
    if (tid == 0)
        g_pool[(size_t)b*512 + ch] = (red[0]+red[1]+red[2]+red[3]) * (1.0f/SP);
}

// ---------------- channel pooling: y2/low half ----------------
__global__ __launch_bounds__(128) void pool_y2low_kernel() {
    int ch = 256 + (blockIdx.x & 255);
    int b = blockIdx.x >> 8;
    int tid = threadIdx.x;
    const float* src;
    if (ch < 448) src = g_y2 + ((size_t)b*192 + (ch-256))*SP;
    else          src = g_low + ((size_t)b*64 + (ch-448))*SP;
    float s = 0.f;
    for (int i = tid; i < SP; i += 128) s += src[i];
#pragma unroll
    for (int off = 16; off > 0; off >>= 1)
        s += __shfl_down_sync(0xffffffffu, s, off);
    __shared__ float red[4];
    if ((tid & 31) == 0) red[tid >> 5] = s;
    __syncthreads();
    if (tid == 0)
        g_pool[(size_t)b*512 + ch] = (red[0]+red[1]+red[2]+red[3]) * (1.0f/SP);
}

// ---------------- softmax over 512 channels ----------------
__global__ __launch_bounds__(512) void smx_kernel() {
    __shared__ float sm[512];
    int b = blockIdx.x, tid = threadIdx.x;
    float p = g_pool[b*512 + tid];
    sm[tid] = p;
    __syncthreads();
    for (int off = 256; off > 0; off >>= 1) {
        if (tid < off) sm[tid] = fmaxf(sm[tid], sm[tid+off]);
        __syncthreads();
    }
    float mx = sm[0];
    __syncthreads();
    float e = expf(p - mx);
    sm[tid] = e;
    __syncthreads();
    for (int off = 256; off > 0; off >>= 1) {
        if (tid < off) sm[tid] += sm[tid+off];
        __syncthreads();
    }
    g_smx[b*512 + tid] = e / sm[0];
}

// ---------------- final gate + fold ----------------
__global__ __launch_bounds__(256) void final_kernel(float* __restrict__ out) {
    int i = blockIdx.x * 256 + threadIdx.x;   // over 4*256*1728
    int s = i % SP;
    int c = (i / SP) & 255;
    int b = i / (SP*256);
    float v1 = g_y1[i];
    float w1 = g_smx[b*512 + c];
    float v2, w2 = g_smx[b*512 + 256 + c];
    if (c < 192) v2 = g_y2[((size_t)b*192 + c)*SP + s];
    else         v2 = g_low[((size_t)b*64 + (c-192))*SP + s];
    out[i] = w1*v1 + w2*v2;
}

// ---------------- launch ----------------
extern "C" void kernel_launch(void* const* d_in, const int* in_sizes, int n_in,
                              void* d_out, int out_size) {
    const float* x      = (const float*)d_in[0];
    const float* w_sq1  = (const float*)d_in[1];
    const float* w_sq2  = (const float*)d_in[2];
    const float* w_pwc2 = (const float*)d_in[3];
    const float* w_conv = (const float*)d_in[4];
    const float* b_conv = (const float*)d_in[5];
    const float* w_q1   = (const float*)d_in[6];
    const float* w_q2   = (const float*)d_in[7];
    const float* w_k1   = (const float*)d_in[8];
    const float* w_k2   = (const float*)d_in[9];
    const float* w_v    = (const float*)d_in[10];
    const float* w_c    = (const float*)d_in[11];
    const float* lq1    = (const float*)d_in[12];
    const float* lk1    = (const float*)d_in[13];
    const float* lq2    = (const float*)d_in[14];
    const float* lk2    = (const float*)d_in[15];
    float* out = (float*)d_out;

    cudaFuncSetAttribute(attn_part_kernel,
                         cudaFuncAttributeMaxDynamicSharedMemorySize, 65536);

    // fork side stream (input-independent subgraph)
    cudaEventRecord(g_evF, 0);
    cudaStreamWaitEvent(g_s1, g_evF, 0);
    wl_kernel<<<672, 192, 0, g_s1>>>(x, w_sq2, w_conv);
    cudaEventRecord(g_evWL, g_s1);                 // g_low + conv weights ready
    pw_kernel<<<dim3(4,24,9), 192, 0, g_s1>>>(w_pwc2);
    pool_y2low_kernel<<<1024, 128, 0, g_s1>>>();
    cudaEventRecord(g_evS1, g_s1);                 // y2/low pool ready

    // critical path
    pw0_kernel<<<288, 192>>>(x, w_sq1);
    qkv_kernel<<<432, 384>>>(w_q1, w_q2, w_k1, w_k2, w_v);
    attn_part_kernel<<<dim3(105,16), 256, 65536>>>();
    comb_proj_kernel<<<dim3(27,4), 256>>>(lq1, lk1, lq2, lk2, w_c);
    cudaStreamWaitEvent(0, g_evWL, 0);             // conv needs g_wtA/B
    conv_kernel<<<dim3(72,4), 128>>>(b_conv);
    pool_y1_kernel<<<1024, 128>>>();
    cudaStreamWaitEvent(0, g_evS1, 0);             // smx needs full g_pool
    smx_kernel<<<4, 512>>>();
    final_kernel<<<6912, 256>>>(out);
}